// round 9
// baseline (speedup 1.0000x reference)
#include <cuda_runtime.h>
#include <cuda_fp16.h>
#include <cstdint>

#define BATCH 4
#define TSEQ  4096

typedef unsigned int u32;

// ---------------- device globals (no alloc allowed) ----------------
// fp16, natural [b][t][32] layout. g_q pre-scaled by 32^-0.5 * log2(e).
__device__ __half g_q[BATCH * TSEQ * 32];
__device__ __half g_k[BATCH * TSEQ * 32];
__device__ __half g_v[BATCH * TSEQ * 32];
__device__ float  g_po[BATCH * 32 * 16 * 128 * 32];  // split partial O
__device__ float  g_pl[BATCH * 32 * 16 * 128];       // split partial l

static __device__ __forceinline__ float fast_exp2(float x) {
    float y; asm("ex2.approx.ftz.f32 %0, %1;" : "=f"(y) : "f"(x)); return y;
}
static __device__ __forceinline__ u32 h2pack(float hi, float lo) {
    u32 d; asm("cvt.rn.f16x2.f32 %0, %1, %2;" : "=r"(d) : "f"(hi), "f"(lo)); return d;
}
static __device__ __forceinline__ u32 smem_u32(const void* p) {
    u32 a;
    asm("{ .reg .u64 t; cvta.to.shared.u64 t, %1; cvt.u32.u64 %0, t; }"
        : "=r"(a) : "l"(p));
    return a;
}
static __device__ __forceinline__ void cpasync16(u32 saddr, const void* g) {
    asm volatile("cp.async.ca.shared.global [%0], [%1], 16;" :: "r"(saddr), "l"(g));
}
#define CP_COMMIT()  asm volatile("cp.async.commit_group;" ::: "memory")
#define CP_WAIT(n)   asm volatile("cp.async.wait_group %0;" :: "n"(n) : "memory")

// D += A*B  (m16n8k16 fp16 inputs, f32 accum)
static __device__ __forceinline__ void mma16(float* d, const u32* a, u32 b0, u32 b1) {
    asm volatile(
        "mma.sync.aligned.m16n8k16.row.col.f32.f16.f16.f32 "
        "{%0,%1,%2,%3}, {%4,%5,%6,%7}, {%8,%9}, {%0,%1,%2,%3};"
        : "+f"(d[0]), "+f"(d[1]), "+f"(d[2]), "+f"(d[3])
        : "r"(a[0]), "r"(a[1]), "r"(a[2]), "r"(a[3]), "r"(b0), "r"(b1));
}
static __device__ __forceinline__ void ldsm4(u32& r0, u32& r1, u32& r2, u32& r3, u32 a) {
    asm volatile("ldmatrix.sync.aligned.m8n8.x4.shared.b16 {%0,%1,%2,%3}, [%4];"
        : "=r"(r0), "=r"(r1), "=r"(r2), "=r"(r3) : "r"(a));
}
static __device__ __forceinline__ void ldsm4t(u32& r0, u32& r1, u32& r2, u32& r3, u32 a) {
    asm volatile("ldmatrix.sync.aligned.m8n8.x4.trans.shared.b16 {%0,%1,%2,%3}, [%4];"
        : "=r"(r0), "=r"(r1), "=r"(r2), "=r"(r3) : "r"(a));
}

// uniform 4-tile splits: qtile qi has n=2(qi+1) key tiles, s_i = ceil((qi+1)/2)
static __device__ __forceinline__ int nsplits(int i) { return (i + 2) >> 1; }

// ---------------------------------------------------------------------------
// Kernel 1: QKV projection -> fp16. 512 blocks x 32 rows, 256 threads.
// All smem traffic via float4 (W rows, x broadcast).
// ---------------------------------------------------------------------------
__global__ __launch_bounds__(256) void qkv_kernel(
    const float* __restrict__ x,
    const float* __restrict__ Wq,
    const float* __restrict__ Wk,
    const float* __restrict__ Wv)
{
    __shared__ float4 sW[3][32 * 9];   // [which][h*9 + d4], row-padded
    __shared__ float4 sx[32 * 9];      // [row*9 + d4]

    int tid = threadIdx.x;
    {
        int hh = tid >> 3, d4 = tid & 7;
        sW[0][hh * 9 + d4] = ((const float4*)Wq)[tid];
        sW[1][hh * 9 + d4] = ((const float4*)Wk)[tid];
        sW[2][hh * 9 + d4] = ((const float4*)Wv)[tid];
        sx[hh * 9 + d4]    = ((const float4*)(x + (size_t)blockIdx.x * 1024))[tid];
    }
    __syncthreads();

    int h = tid & 31, rr = tid >> 5;
    float aq[4] = {0.f, 0.f, 0.f, 0.f};
    float ak[4] = {0.f, 0.f, 0.f, 0.f};
    float av[4] = {0.f, 0.f, 0.f, 0.f};
#pragma unroll
    for (int d4 = 0; d4 < 8; d4++) {
        float4 wq = sW[0][h * 9 + d4];
        float4 wk = sW[1][h * 9 + d4];
        float4 wv = sW[2][h * 9 + d4];
#pragma unroll
        for (int s2 = 0; s2 < 4; s2++) {
            float4 xv = sx[(rr + 8 * s2) * 9 + d4];   // uniform per warp
            aq[s2] = fmaf(xv.x, wq.x, fmaf(xv.y, wq.y, fmaf(xv.z, wq.z, fmaf(xv.w, wq.w, aq[s2]))));
            ak[s2] = fmaf(xv.x, wk.x, fmaf(xv.y, wk.y, fmaf(xv.z, wk.z, fmaf(xv.w, wk.w, ak[s2]))));
            av[s2] = fmaf(xv.x, wv.x, fmaf(xv.y, wv.y, fmaf(xv.z, wv.z, fmaf(xv.w, wv.w, av[s2]))));
        }
    }
    const float QS = 0.17677669529663687f * 1.4426950408889634f; // 32^-0.5 * log2e
    int rowbase = blockIdx.x * 32;
#pragma unroll
    for (int s2 = 0; s2 < 4; s2++) {
        int row = rowbase + rr + 8 * s2;
        g_q[row * 32 + h] = __float2half_rn(aq[s2] * QS);
        g_k[row * 32 + h] = __float2half_rn(ak[s2]);
        g_v[row * 32 + h] = __float2half_rn(av[s2]);
    }
}

// ---------------------------------------------------------------------------
// Kernel 2: fp16 m16n8k16 flash attention (no-max softmax, uniform split-KV).
// CTA = 256 threads = 8 warps x 16 q-rows; 64-key tiles, double-buffered
// cp.async, ONE __syncthreads per tile. Mainloop walks 16-key groups with
// all ldmatrix issued up-front and two independent S-mma chains.
// ---------------------------------------------------------------------------
__global__ __launch_bounds__(256, 3) void attn_kernel(float* __restrict__ out)
{
    __shared__ __align__(128) char sK[2][64 * 64];   // [key][dim] fp16, swizzled
    __shared__ __align__(128) char sV[2][64 * 64];

    int tid  = threadIdx.x;
    int lane = tid & 31;
    int w    = tid >> 5;
    int g    = lane >> 2;     // group id 0..7
    int t4   = lane & 3;      // thread in group
    int b    = blockIdx.y;

    // map blockIdx.x -> (qtile qi, split p)
    int u = blockIdx.x, qi = 0, s = 1;
    for (qi = 0; qi < 32; qi++) {
        s = nsplits(qi);
        if (u < s) break;
        u -= s;
    }
    int p  = u;
    int n  = 2 * (qi + 1);
    int tb = p * 4;
    int te = (tb + 4 < n) ? tb + 4 : n;
    int r0 = qi * 128;
    int rA = r0 + 16 * w + g;     // this lane's first q-row (second = rA+8)

    u32 sKb[2] = { smem_u32(&sK[0][0]), smem_u32(&sK[1][0]) };
    u32 sVb[2] = { smem_u32(&sV[0][0]), smem_u32(&sV[1][0]) };

    // cp.async staging offset (swizzle chunk ^ ((row>>1)&3))
    u32 stoff = (u32)((tid >> 2) * 64 + (((tid & 3) ^ ((tid >> 3) & 3)) << 4));
    u32 goff  = (u32)((tid >> 2) * 64 + (tid & 3) * 16);
    // ldmatrix K address offset
    u32 klm = (u32)((lane & 7) * 64 + ((((lane >> 3) ^ (((lane & 7) >> 1) & 3))) << 4));
    // ldmatrix V lane mapping
    int vkey = (lane & 7) + 8 * ((lane >> 3) & 1);
    int vch  = (lane >> 4);

    // ---- Q fragments ----
    u32 qa[2][4];
    {
        const __half* qA = g_q + ((size_t)b * TSEQ + rA) * 32;
        const __half* qB = qA + 8 * 32;
#pragma unroll
        for (int ks = 0; ks < 2; ks++) {
            qa[ks][0] = *(const u32*)(qA + 16 * ks + 2 * t4);
            qa[ks][1] = *(const u32*)(qB + 16 * ks + 2 * t4);
            qa[ks][2] = *(const u32*)(qA + 16 * ks + 2 * t4 + 8);
            qa[ks][3] = *(const u32*)(qB + 16 * ks + 2 * t4 + 8);
        }
    }

    float oc[4][4];
#pragma unroll
    for (int jd = 0; jd < 4; jd++)
#pragma unroll
        for (int q = 0; q < 4; q++) oc[jd][q] = 0.f;
    float ls0 = 0.f, ls1 = 0.f;

    // ---- stage first tile into buffer 0 ----
    {
        const char* kg = (const char*)(g_k + ((size_t)b * TSEQ + tb * 64) * 32);
        const char* vg = (const char*)(g_v + ((size_t)b * TSEQ + tb * 64) * 32);
        cpasync16(sKb[0] + stoff, kg + goff);
        cpasync16(sVb[0] + stoff, vg + goff);
        CP_COMMIT();
    }

    int cur = 0;

    for (int t = tb; t < te; t++) {
        CP_WAIT(0);
        __syncthreads();   // publishes tile t; all warps past tile t-1 compute

        if (t + 1 < te) {  // prefetch t+1 into the buffer tile t-1 used
            const char* kg = (const char*)(g_k + ((size_t)b * TSEQ + (t + 1) * 64) * 32);
            const char* vg = (const char*)(g_v + ((size_t)b * TSEQ + (t + 1) * 64) * 32);
            cpasync16(sKb[cur ^ 1] + stoff, kg + goff);
            cpasync16(sVb[cur ^ 1] + stoff, vg + goff);
            CP_COMMIT();
        }

        u32 cK = sKb[cur];
        u32 cV = sVb[cur];
        bool domask = (t >= 2 * qi);

#pragma unroll
        for (int c = 0; c < 4; c++) {      // 16-key groups
            // ---- V frags first (latency hidden under S+exp) ----
            u32 vb[8];
            {
                int key = c * 16 + vkey;
                u32 vrow = cV + (u32)(key * 64);
                ldsm4t(vb[0], vb[1], vb[2], vb[3],
                       vrow + (u32)(((vch)     ^ ((key >> 1) & 3)) << 4));
                ldsm4t(vb[4], vb[5], vb[6], vb[7],
                       vrow + (u32)(((vch + 2) ^ ((key >> 1) & 3)) << 4));
            }
            // ---- both K chunks up-front ----
            u32 k0, k1, k2, k3, k4, k5, k6, k7;
            ldsm4(k0, k1, k2, k3, cK + (u32)((2 * c)     * 512) + klm);
            ldsm4(k4, k5, k6, k7, cK + (u32)((2 * c + 1) * 512) + klm);

            // ---- two independent S chains ----
            float sa[4] = {0.f, 0.f, 0.f, 0.f};
            float sb[4] = {0.f, 0.f, 0.f, 0.f};
            mma16(sa, qa[0], k0, k1);
            mma16(sb, qa[0], k4, k5);
            mma16(sa, qa[1], k2, k3);
            mma16(sb, qa[1], k6, k7);

            // ---- mask + exp + row-sum + pack ----
            int ct = t * 64 + 16 * c + 2 * t4;
            float a0 = fast_exp2(sa[0]);
            float a1 = fast_exp2(sa[1]);
            float a2 = fast_exp2(sa[2]);
            float a3 = fast_exp2(sa[3]);
            float b0 = fast_exp2(sb[0]);
            float b1 = fast_exp2(sb[1]);
            float b2 = fast_exp2(sb[2]);
            float b3 = fast_exp2(sb[3]);
            if (domask) {
                if (ct     > rA)     a0 = 0.f;
                if (ct + 1 > rA)     a1 = 0.f;
                if (ct     > rA + 8) a2 = 0.f;
                if (ct + 1 > rA + 8) a3 = 0.f;
                if (ct + 8 > rA)     b0 = 0.f;
                if (ct + 9 > rA)     b1 = 0.f;
                if (ct + 8 > rA + 8) b2 = 0.f;
                if (ct + 9 > rA + 8) b3 = 0.f;
            }
            ls0 += (a0 + a1) + (b0 + b1);
            ls1 += (a2 + a3) + (b2 + b3);
            u32 pav[4];
            pav[0] = h2pack(a1, a0);
            pav[1] = h2pack(a3, a2);
            pav[2] = h2pack(b1, b0);
            pav[3] = h2pack(b3, b2);

            // ---- PV ----
            mma16(oc[0], pav, vb[0], vb[1]);
            mma16(oc[1], pav, vb[2], vb[3]);
            mma16(oc[2], pav, vb[4], vb[5]);
            mma16(oc[3], pav, vb[6], vb[7]);
        }

        cur ^= 1;
    }

    // ---- row-sum reduction across the 4 lanes of each row group ----
    ls0 += __shfl_xor_sync(0xffffffffu, ls0, 1);
    ls0 += __shfl_xor_sync(0xffffffffu, ls0, 2);
    ls1 += __shfl_xor_sync(0xffffffffu, ls1, 1);
    ls1 += __shfl_xor_sync(0xffffffffu, ls1, 2);

    // ---- epilogue ----
    if (s == 1) {
        float i0 = 1.0f / ls0;
        float i1 = 1.0f / ls1;
        float* oA = out + ((size_t)b * TSEQ + rA) * 32;
        float* oB = oA + 8 * 32;
#pragma unroll
        for (int jd = 0; jd < 4; jd++) {
            *(float2*)&oA[8 * jd + 2 * t4] = make_float2(oc[jd][0] * i0, oc[jd][1] * i0);
            *(float2*)&oB[8 * jd + 2 * t4] = make_float2(oc[jd][2] * i1, oc[jd][3] * i1);
        }
    } else {
        size_t base = ((size_t)(b * 32 + qi) * 16 + p) * 128;
        int lr = 16 * w + g;
        float* pA = g_po + (base + lr) * 32;
        float* pB = pA + 8 * 32;
#pragma unroll
        for (int jd = 0; jd < 4; jd++) {
            *(float2*)&pA[8 * jd + 2 * t4] = make_float2(oc[jd][0], oc[jd][1]);
            *(float2*)&pB[8 * jd + 2 * t4] = make_float2(oc[jd][2], oc[jd][3]);
        }
        if (t4 == 0) {
            g_pl[base + lr]     = ls0;
            g_pl[base + lr + 8] = ls1;
        }
    }
}

// ---------------------------------------------------------------------------
// Kernel 3: combine split partials: out = sum_p O_p / sum_p l_p
// ---------------------------------------------------------------------------
__global__ __launch_bounds__(128) void combine_kernel(float* __restrict__ out)
{
    int qi = blockIdx.x, b = blockIdx.y, r = threadIdx.x;
    int s = nsplits(qi);
    if (s < 2) return;

    float l = 0.f;
    for (int p = 0; p < s; p++)
        l += g_pl[((size_t)(b * 32 + qi) * 16 + p) * 128 + r];
    float inv = 1.0f / l;

    float4 o[8];
#pragma unroll
    for (int j = 0; j < 8; j++) o[j] = make_float4(0.f, 0.f, 0.f, 0.f);
    for (int p = 0; p < s; p++) {
        const float4* pp = (const float4*)(g_po +
            (((size_t)(b * 32 + qi) * 16 + p) * 128 + r) * 32);
#pragma unroll
        for (int j = 0; j < 8; j++) {
            float4 a = pp[j];
            o[j].x += a.x; o[j].y += a.y; o[j].z += a.z; o[j].w += a.w;
        }
    }
    float4* op = (float4*)(out + ((size_t)b * TSEQ + qi * 128 + r) * 32);
#pragma unroll
    for (int j = 0; j < 8; j++) {
        o[j].x *= inv; o[j].y *= inv; o[j].z *= inv; o[j].w *= inv;
        op[j] = o[j];
    }
}

// ---------------------------------------------------------------------------
extern "C" void kernel_launch(void* const* d_in, const int* in_sizes, int n_in,
                              void* d_out, int out_size)
{
    const float* x  = (const float*)d_in[0];
    const float* Wq = (const float*)d_in[1];
    const float* Wk = (const float*)d_in[2];
    const float* Wv = (const float*)d_in[3];
    float* out = (float*)d_out;

    qkv_kernel<<<(BATCH * TSEQ) / 32, 256>>>(x, Wq, Wk, Wv);

    dim3 grid(272, BATCH);              // sum_i ceil((i+1)/2) = 272 per batch
    attn_kernel<<<grid, 256>>>(out);

    combine_kernel<<<dim3(32, BATCH), 128>>>(out);
}

// round 10
// speedup vs baseline: 1.4122x; 1.4122x over previous
#include <cuda_runtime.h>
#include <cuda_fp16.h>
#include <cstdint>

#define BATCH 4
#define TSEQ  4096

typedef unsigned int u32;

// ---------------- device globals (no alloc allowed) ----------------
// fp16, natural [b][t][32] layout. g_q pre-scaled by 32^-0.5 * log2(e).
__device__ __half g_q[BATCH * TSEQ * 32];
__device__ __half g_k[BATCH * TSEQ * 32];
__device__ __half g_v[BATCH * TSEQ * 32];
__device__ float  g_po[BATCH * 32 * 16 * 128 * 32];  // split partial O
__device__ float  g_pl[BATCH * 32 * 16 * 128];       // split partial l

static __device__ __forceinline__ u32 h2pack(float hi, float lo) {
    u32 d; asm("cvt.rn.f16x2.f32 %0, %1, %2;" : "=r"(d) : "f"(hi), "f"(lo)); return d;
}
static __device__ __forceinline__ u32 h2exp(u32 x) {
    u32 y; asm("ex2.approx.f16x2 %0, %1;" : "=r"(y) : "r"(x)); return y;
}
static __device__ __forceinline__ u32 smem_u32(const void* p) {
    u32 a;
    asm("{ .reg .u64 t; cvta.to.shared.u64 t, %1; cvt.u32.u64 %0, t; }"
        : "=r"(a) : "l"(p));
    return a;
}
static __device__ __forceinline__ void cpasync16(u32 saddr, const void* g) {
    asm volatile("cp.async.ca.shared.global [%0], [%1], 16;" :: "r"(saddr), "l"(g));
}
#define CP_COMMIT()  asm volatile("cp.async.commit_group;" ::: "memory")
#define CP_WAIT(n)   asm volatile("cp.async.wait_group %0;" :: "n"(n) : "memory")

// D += A*B  (m16n8k16 fp16 inputs, f32 accum)
static __device__ __forceinline__ void mma16(float* d, const u32* a, u32 b0, u32 b1) {
    asm volatile(
        "mma.sync.aligned.m16n8k16.row.col.f32.f16.f16.f32 "
        "{%0,%1,%2,%3}, {%4,%5,%6,%7}, {%8,%9}, {%0,%1,%2,%3};"
        : "+f"(d[0]), "+f"(d[1]), "+f"(d[2]), "+f"(d[3])
        : "r"(a[0]), "r"(a[1]), "r"(a[2]), "r"(a[3]), "r"(b0), "r"(b1));
}
static __device__ __forceinline__ void ldsm4(u32& r0, u32& r1, u32& r2, u32& r3, u32 a) {
    asm volatile("ldmatrix.sync.aligned.m8n8.x4.shared.b16 {%0,%1,%2,%3}, [%4];"
        : "=r"(r0), "=r"(r1), "=r"(r2), "=r"(r3) : "r"(a));
}
static __device__ __forceinline__ void ldsm4t(u32& r0, u32& r1, u32& r2, u32& r3, u32 a) {
    asm volatile("ldmatrix.sync.aligned.m8n8.x4.trans.shared.b16 {%0,%1,%2,%3}, [%4];"
        : "=r"(r0), "=r"(r1), "=r"(r2), "=r"(r3) : "r"(a));
}

// uniform 4-tile splits: qtile qi has n=2(qi+1) key tiles, s_i = ceil((qi+1)/2)
static __device__ __forceinline__ int nsplits(int i) { return (i + 2) >> 1; }

// ---------------------------------------------------------------------------
// Kernel 1: QKV projection -> fp16. 256 blocks x 64 rows, 256 threads.
// ---------------------------------------------------------------------------
__global__ __launch_bounds__(256) void qkv_kernel(
    const float* __restrict__ x,
    const float* __restrict__ Wq,
    const float* __restrict__ Wk,
    const float* __restrict__ Wv)
{
    __shared__ float sW[3][32 * 33];
    __shared__ float sx[64 * 32];

    int tid = threadIdx.x;
    for (int i = tid; i < 1024; i += 256) {
        int hh = i >> 5, dd = i & 31;
        sW[0][dd * 33 + hh] = Wq[i];
        sW[1][dd * 33 + hh] = Wk[i];
        sW[2][dd * 33 + hh] = Wv[i];
    }
#pragma unroll
    for (int i = 0; i < 2; i++)
        ((float4*)sx)[tid + 256 * i] =
            ((const float4*)(x + (size_t)blockIdx.x * 2048))[tid + 256 * i];
    __syncthreads();

    int h = tid & 31, rr = tid >> 5;
    float aq[8], ak[8], av[8];
#pragma unroll
    for (int s2 = 0; s2 < 8; s2++) { aq[s2] = 0.f; ak[s2] = 0.f; av[s2] = 0.f; }
#pragma unroll
    for (int d = 0; d < 32; d++) {
        float wq = sW[0][d * 33 + h];
        float wk = sW[1][d * 33 + h];
        float wv = sW[2][d * 33 + h];
#pragma unroll
        for (int s2 = 0; s2 < 8; s2++) {
            float xv = sx[(rr + 8 * s2) * 32 + d];   // warp broadcast
            aq[s2] = fmaf(xv, wq, aq[s2]);
            ak[s2] = fmaf(xv, wk, ak[s2]);
            av[s2] = fmaf(xv, wv, av[s2]);
        }
    }
    const float QS = 0.17677669529663687f * 1.4426950408889634f; // 32^-0.5 * log2e
    int rowbase = blockIdx.x * 64;
#pragma unroll
    for (int s2 = 0; s2 < 8; s2++) {
        int row = rowbase + rr + 8 * s2;
        g_q[row * 32 + h] = __float2half_rn(aq[s2] * QS);
        g_k[row * 32 + h] = __float2half_rn(ak[s2]);
        g_v[row * 32 + h] = __float2half_rn(av[s2]);
    }
}

// ---------------------------------------------------------------------------
// Kernel 2: fp16 m16n8k16 flash attention (no-max softmax, uniform split-KV).
// Structure identical to the proven R8 kernel; softmax path changed to
// packed fp16 ex2 (half the MUFU ops) and row-sums computed by an extra
// ones-column MMA (l = P·1) with a constant B fragment.
// ---------------------------------------------------------------------------
__global__ __launch_bounds__(256, 3) void attn_kernel(float* __restrict__ out)
{
    __shared__ __align__(128) char sK[2][64 * 64];   // [key][dim] fp16, swizzled
    __shared__ __align__(128) char sV[2][64 * 64];

    int tid  = threadIdx.x;
    int lane = tid & 31;
    int w    = tid >> 5;
    int g    = lane >> 2;     // group id 0..7
    int t4   = lane & 3;      // thread in group
    int b    = blockIdx.y;

    // map blockIdx.x -> (qtile qi, split p)
    int u = blockIdx.x, qi = 0, s = 1;
    for (qi = 0; qi < 32; qi++) {
        s = nsplits(qi);
        if (u < s) break;
        u -= s;
    }
    int p  = u;
    int n  = 2 * (qi + 1);
    int tb = p * 4;
    int te = (tb + 4 < n) ? tb + 4 : n;
    int r0 = qi * 128;
    int rA = r0 + 16 * w + g;     // this lane's first q-row (second = rA+8)

    u32 sKb[2] = { smem_u32(&sK[0][0]), smem_u32(&sK[1][0]) };
    u32 sVb[2] = { smem_u32(&sV[0][0]), smem_u32(&sV[1][0]) };

    // cp.async staging offset (swizzle chunk ^ ((row>>1)&3))
    u32 stoff = (u32)((tid >> 2) * 64 + (((tid & 3) ^ ((tid >> 3) & 3)) << 4));
    // ldmatrix K address offset
    u32 klm = (u32)((lane & 7) * 64 + ((((lane >> 3) ^ (((lane & 7) >> 1) & 3))) << 4));
    // ldmatrix V lane mapping
    int vkey = (lane & 7) + 8 * ((lane >> 3) & 1);
    int vch  = (lane >> 4);

    // ones-column B fragment for l = P·1 (n==0 column all ones)
    u32 bl = (g == 0) ? 0x3C003C00u : 0u;

    // ---- Q fragments ----
    u32 qa[2][4];
    {
        const __half* qA = g_q + ((size_t)b * TSEQ + rA) * 32;
        const __half* qB = qA + 8 * 32;
#pragma unroll
        for (int ks = 0; ks < 2; ks++) {
            qa[ks][0] = *(const u32*)(qA + 16 * ks + 2 * t4);
            qa[ks][1] = *(const u32*)(qB + 16 * ks + 2 * t4);
            qa[ks][2] = *(const u32*)(qA + 16 * ks + 2 * t4 + 8);
            qa[ks][3] = *(const u32*)(qB + 16 * ks + 2 * t4 + 8);
        }
    }

    float oc[4][4];
#pragma unroll
    for (int jd = 0; jd < 4; jd++)
#pragma unroll
        for (int q = 0; q < 4; q++) oc[jd][q] = 0.f;
    float lc[4] = {0.f, 0.f, 0.f, 0.f};   // l accumulator (col 0 meaningful)

    // ---- stage tile tb into buffer 0 ----
    {
        const char* kg = (const char*)(g_k + ((size_t)b * TSEQ + tb * 64) * 32);
        const char* vg = (const char*)(g_v + ((size_t)b * TSEQ + tb * 64) * 32);
        u32 goff = (u32)((tid >> 2) * 64 + (tid & 3) * 16);
        cpasync16(sKb[0] + stoff, kg + goff);
        cpasync16(sVb[0] + stoff, vg + goff);
        CP_COMMIT();
    }

    int cur = 0;

    for (int t = tb; t < te; t++) {
        bool havenext = (t + 1 < te);
        if (havenext) {
            const char* kg = (const char*)(g_k + ((size_t)b * TSEQ + (t + 1) * 64) * 32);
            const char* vg = (const char*)(g_v + ((size_t)b * TSEQ + (t + 1) * 64) * 32);
            u32 goff = (u32)((tid >> 2) * 64 + (tid & 3) * 16);
            cpasync16(sKb[cur ^ 1] + stoff, kg + goff);
            cpasync16(sVb[cur ^ 1] + stoff, vg + goff);
            CP_COMMIT();
            CP_WAIT(1);
        } else {
            CP_WAIT(0);
        }
        __syncthreads();

        u32 cK = sKb[cur];
        u32 cV = sVb[cur];
        bool domask = (t >= 2 * qi);

        u32 pp01 = 0, pp23 = 0;   // packed scores of even chunk, pending PV

#pragma unroll
        for (int j = 0; j < 8; j++) {
            // ---- K frags: one ldmatrix.x4 per 8-key chunk ----
            u32 kb0, kb1, kb2, kb3;
            ldsm4(kb0, kb1, kb2, kb3, cK + (u32)(j * 512) + klm);

            float sa[4] = {0.f, 0.f, 0.f, 0.f};
            mma16(sa, qa[0], kb0, kb1);
            mma16(sa, qa[1], kb2, kb3);

            // ---- mask (pre-exp) + pack to fp16 pairs ----
            int ct = t * 64 + 8 * j + 2 * t4;
            if (domask) {
                if (ct     > rA)     sa[0] = -1e30f;   // -> fp16 -inf -> exp 0
                if (ct + 1 > rA)     sa[1] = -1e30f;
                if (ct     > rA + 8) sa[2] = -1e30f;
                if (ct + 1 > rA + 8) sa[3] = -1e30f;
            }
            u32 p01 = h2pack(sa[1], sa[0]);
            u32 p23 = h2pack(sa[3], sa[2]);

            if ((j & 1) == 0) {
                pp01 = p01; pp23 = p23;
            } else {
                // ---- packed exp: P frags for the 16-key group c = j>>1 ----
                u32 pa[4];
                pa[0] = h2exp(pp01);
                pa[1] = h2exp(pp23);
                pa[2] = h2exp(p01);
                pa[3] = h2exp(p23);
                int c = j >> 1;
#pragma unroll
                for (int pr = 0; pr < 2; pr++) {
                    u32 vb0, vb1, vb2, vb3;
                    int key = c * 16 + vkey;
                    int ch  = 2 * pr + vch;
                    u32 va = cV + (u32)(key * 64 + ((ch ^ ((key >> 1) & 3)) << 4));
                    ldsm4t(vb0, vb1, vb2, vb3, va);
                    mma16(oc[2 * pr],     pa, vb0, vb1);
                    mma16(oc[2 * pr + 1], pa, vb2, vb3);
                }
                mma16(lc, pa, bl, bl);       // l += P · ones-column
            }
        }

        __syncthreads();
        cur ^= 1;
    }

    // ---- extract row sums: l lives in col 0 (t4==0 lanes), c0/c2 ----
    float ls0 = __shfl_sync(0xffffffffu, lc[0], lane & ~3);
    float ls1 = __shfl_sync(0xffffffffu, lc[2], lane & ~3);

    // ---- epilogue ----
    if (s == 1) {
        float i0 = 1.0f / ls0;
        float i1 = 1.0f / ls1;
        float* oA = out + ((size_t)b * TSEQ + rA) * 32;
        float* oB = oA + 8 * 32;
#pragma unroll
        for (int jd = 0; jd < 4; jd++) {
            *(float2*)&oA[8 * jd + 2 * t4] = make_float2(oc[jd][0] * i0, oc[jd][1] * i0);
            *(float2*)&oB[8 * jd + 2 * t4] = make_float2(oc[jd][2] * i1, oc[jd][3] * i1);
        }
    } else {
        size_t base = ((size_t)(b * 32 + qi) * 16 + p) * 128;
        int lr = 16 * w + g;
        float* pA = g_po + (base + lr) * 32;
        float* pB = pA + 8 * 32;
#pragma unroll
        for (int jd = 0; jd < 4; jd++) {
            *(float2*)&pA[8 * jd + 2 * t4] = make_float2(oc[jd][0], oc[jd][1]);
            *(float2*)&pB[8 * jd + 2 * t4] = make_float2(oc[jd][2], oc[jd][3]);
        }
        if (t4 == 0) {
            g_pl[base + lr]     = ls0;
            g_pl[base + lr + 8] = ls1;
        }
    }
}

// ---------------------------------------------------------------------------
// Kernel 3: combine split partials: out = sum_p O_p / sum_p l_p
// ---------------------------------------------------------------------------
__global__ __launch_bounds__(128) void combine_kernel(float* __restrict__ out)
{
    int qi = blockIdx.x, b = blockIdx.y, r = threadIdx.x;
    int s = nsplits(qi);
    if (s < 2) return;

    float l = 0.f;
    for (int p = 0; p < s; p++)
        l += g_pl[((size_t)(b * 32 + qi) * 16 + p) * 128 + r];
    float inv = 1.0f / l;

    float4 o[8];
#pragma unroll
    for (int j = 0; j < 8; j++) o[j] = make_float4(0.f, 0.f, 0.f, 0.f);
    for (int p = 0; p < s; p++) {
        const float4* pp = (const float4*)(g_po +
            (((size_t)(b * 32 + qi) * 16 + p) * 128 + r) * 32);
#pragma unroll
        for (int j = 0; j < 8; j++) {
            float4 a = pp[j];
            o[j].x += a.x; o[j].y += a.y; o[j].z += a.z; o[j].w += a.w;
        }
    }
    float4* op = (float4*)(out + ((size_t)b * TSEQ + qi * 128 + r) * 32);
#pragma unroll
    for (int j = 0; j < 8; j++) {
        o[j].x *= inv; o[j].y *= inv; o[j].z *= inv; o[j].w *= inv;
        op[j] = o[j];
    }
}

// ---------------------------------------------------------------------------
extern "C" void kernel_launch(void* const* d_in, const int* in_sizes, int n_in,
                              void* d_out, int out_size)
{
    const float* x  = (const float*)d_in[0];
    const float* Wq = (const float*)d_in[1];
    const float* Wk = (const float*)d_in[2];
    const float* Wv = (const float*)d_in[3];
    float* out = (float*)d_out;

    qkv_kernel<<<(BATCH * TSEQ) / 64, 256>>>(x, Wq, Wk, Wv);

    dim3 grid(272, BATCH);              // sum_i ceil((i+1)/2) = 272 per batch
    attn_kernel<<<grid, 256>>>(out);

    combine_kernel<<<dim3(32, BATCH), 128>>>(out);
}

// round 11
// speedup vs baseline: 1.5488x; 1.0967x over previous
#include <cuda_runtime.h>
#include <cuda_fp16.h>
#include <cstdint>

#define BATCH 4
#define TSEQ  4096

typedef unsigned int u32;

// ---------------- device globals (no alloc allowed) ----------------
// fp16, natural [b][t][32] layout. g_q pre-scaled by 32^-0.5 * log2(e).
__device__ __half g_q[BATCH * TSEQ * 32];
__device__ __half g_k[BATCH * TSEQ * 32];
__device__ __half g_v[BATCH * TSEQ * 32];
__device__ float  g_po[BATCH * 32 * 16 * 128 * 32];  // split partial O
__device__ float  g_pl[BATCH * 32 * 16 * 128];       // split partial l

static __device__ __forceinline__ u32 h2pack(float hi, float lo) {
    u32 d; asm("cvt.rn.f16x2.f32 %0, %1, %2;" : "=r"(d) : "f"(hi), "f"(lo)); return d;
}
static __device__ __forceinline__ u32 h2exp(u32 x) {
    u32 y; asm("ex2.approx.f16x2 %0, %1;" : "=r"(y) : "r"(x)); return y;
}
static __device__ __forceinline__ u32 smem_u32(const void* p) {
    u32 a;
    asm("{ .reg .u64 t; cvta.to.shared.u64 t, %1; cvt.u32.u64 %0, t; }"
        : "=r"(a) : "l"(p));
    return a;
}
static __device__ __forceinline__ void cpasync16(u32 saddr, const void* g) {
    asm volatile("cp.async.ca.shared.global [%0], [%1], 16;" :: "r"(saddr), "l"(g));
}
#define CP_COMMIT()  asm volatile("cp.async.commit_group;" ::: "memory")
#define CP_WAIT(n)   asm volatile("cp.async.wait_group %0;" :: "n"(n) : "memory")

// D += A*B  (m16n8k16 fp16 inputs, f32 accum)
static __device__ __forceinline__ void mma16(float* d, const u32* a, u32 b0, u32 b1) {
    asm volatile(
        "mma.sync.aligned.m16n8k16.row.col.f32.f16.f16.f32 "
        "{%0,%1,%2,%3}, {%4,%5,%6,%7}, {%8,%9}, {%0,%1,%2,%3};"
        : "+f"(d[0]), "+f"(d[1]), "+f"(d[2]), "+f"(d[3])
        : "r"(a[0]), "r"(a[1]), "r"(a[2]), "r"(a[3]), "r"(b0), "r"(b1));
}
static __device__ __forceinline__ void ldsm4(u32& r0, u32& r1, u32& r2, u32& r3, u32 a) {
    asm volatile("ldmatrix.sync.aligned.m8n8.x4.shared.b16 {%0,%1,%2,%3}, [%4];"
        : "=r"(r0), "=r"(r1), "=r"(r2), "=r"(r3) : "r"(a));
}
static __device__ __forceinline__ void ldsm4t(u32& r0, u32& r1, u32& r2, u32& r3, u32 a) {
    asm volatile("ldmatrix.sync.aligned.m8n8.x4.trans.shared.b16 {%0,%1,%2,%3}, [%4];"
        : "=r"(r0), "=r"(r1), "=r"(r2), "=r"(r3) : "r"(a));
}

// uniform 4-tile splits: qtile qi has n=2(qi+1) key tiles, s_i = ceil((qi+1)/2)
static __device__ __forceinline__ int nsplits(int i) { return (i + 2) >> 1; }

// ---------------------------------------------------------------------------
// Kernel 1: QKV projection on tensor cores. 256 CTAs x 64 rows, 128 threads.
// y[row][h] = sum_d x[row][d] * W[h][d]  ==  S = Q·K^T geometry (n=h, k=d).
// All 3 W matrices staged fp16-swizzled in smem (QS folded into Wq).
// ---------------------------------------------------------------------------
__global__ __launch_bounds__(128) void qkv_kernel(
    const float* __restrict__ x,
    const float* __restrict__ Wq,
    const float* __restrict__ Wk,
    const float* __restrict__ Wv)
{
    __shared__ __align__(128) char sW[3][2048];   // [m][h*64B row, swizzled]

    int tid  = threadIdx.x;
    int lane = tid & 31;
    int w    = tid >> 5;
    int g    = lane >> 2;
    int t4   = lane & 3;

    // ---- stage W: thread handles chunk (h = tid>>2, c = tid&3) of each matrix
    {
        int h = tid >> 2, c = tid & 3;
        const float QS = 0.17677669529663687f * 1.4426950408889634f; // 32^-0.5*log2e
        const float* Ws[3] = { Wq, Wk, Wv };
        u32 off = (u32)(h * 64 + ((c ^ ((h >> 1) & 3)) << 4));
#pragma unroll
        for (int m = 0; m < 3; m++) {
            const float4* wp = (const float4*)(Ws[m] + h * 32 + c * 8);
            float4 w0 = wp[0], w1 = wp[1];
            float sc = (m == 0) ? QS : 1.0f;
            uint4 pk;
            pk.x = h2pack(w0.y * sc, w0.x * sc);
            pk.y = h2pack(w0.w * sc, w0.z * sc);
            pk.z = h2pack(w1.y * sc, w1.x * sc);
            pk.w = h2pack(w1.w * sc, w1.z * sc);
            *(uint4*)(sW[m] + off) = pk;
        }
    }

    // ---- A fragments: rows (rA, rA+8), fp32 x -> packed fp16 ----
    int rA = blockIdx.x * 64 + 16 * w + g;
    u32 qa[2][4];
#pragma unroll
    for (int ks = 0; ks < 2; ks++) {
        const float* xA = x + (size_t)rA * 32 + 16 * ks;
        const float* xB = xA + 8 * 32;
        float2 f0 = *(const float2*)(xA + 2 * t4);
        float2 f1 = *(const float2*)(xB + 2 * t4);
        float2 f2 = *(const float2*)(xA + 2 * t4 + 8);
        float2 f3 = *(const float2*)(xB + 2 * t4 + 8);
        qa[ks][0] = h2pack(f0.y, f0.x);
        qa[ks][1] = h2pack(f1.y, f1.x);
        qa[ks][2] = h2pack(f2.y, f2.x);
        qa[ks][3] = h2pack(f3.y, f3.x);
    }
    __syncthreads();

    u32 wlm = (u32)((lane & 7) * 64 + ((((lane >> 3) ^ (((lane & 7) >> 1) & 3))) << 4));
    u32 sWb[3] = { smem_u32(sW[0]), smem_u32(sW[1]), smem_u32(sW[2]) };
    __half* dsts[3] = { g_q, g_k, g_v };

#pragma unroll
    for (int m = 0; m < 3; m++) {
        __half* dst = dsts[m];
#pragma unroll
        for (int j = 0; j < 4; j++) {       // n-tile: outputs h = 8j..8j+7
            u32 b0, b1, b2, b3;
            ldsm4(b0, b1, b2, b3, sWb[m] + (u32)(j * 512) + wlm);
            float c[4] = {0.f, 0.f, 0.f, 0.f};
            mma16(c, qa[0], b0, b1);
            mma16(c, qa[1], b2, b3);
            int col = j * 8 + 2 * t4;
            *(u32*)(dst + (size_t)rA * 32 + col)       = h2pack(c[1], c[0]);
            *(u32*)(dst + (size_t)(rA + 8) * 32 + col) = h2pack(c[3], c[2]);
        }
    }
}

// ---------------------------------------------------------------------------
// Kernel 2: fp16 m16n8k16 flash attention (no-max softmax, uniform split-KV).
// UNCHANGED from the 41.0us baseline.
// ---------------------------------------------------------------------------
__global__ __launch_bounds__(256, 3) void attn_kernel(float* __restrict__ out)
{
    __shared__ __align__(128) char sK[2][64 * 64];   // [key][dim] fp16, swizzled
    __shared__ __align__(128) char sV[2][64 * 64];

    int tid  = threadIdx.x;
    int lane = tid & 31;
    int w    = tid >> 5;
    int g    = lane >> 2;     // group id 0..7
    int t4   = lane & 3;      // thread in group
    int b    = blockIdx.y;

    // map blockIdx.x -> (qtile qi, split p)
    int u = blockIdx.x, qi = 0, s = 1;
    for (qi = 0; qi < 32; qi++) {
        s = nsplits(qi);
        if (u < s) break;
        u -= s;
    }
    int p  = u;
    int n  = 2 * (qi + 1);
    int tb = p * 4;
    int te = (tb + 4 < n) ? tb + 4 : n;
    int r0 = qi * 128;
    int rA = r0 + 16 * w + g;     // this lane's first q-row (second = rA+8)

    u32 sKb[2] = { smem_u32(&sK[0][0]), smem_u32(&sK[1][0]) };
    u32 sVb[2] = { smem_u32(&sV[0][0]), smem_u32(&sV[1][0]) };

    // cp.async staging offset (swizzle chunk ^ ((row>>1)&3))
    u32 stoff = (u32)((tid >> 2) * 64 + (((tid & 3) ^ ((tid >> 3) & 3)) << 4));
    // ldmatrix K address offset
    u32 klm = (u32)((lane & 7) * 64 + ((((lane >> 3) ^ (((lane & 7) >> 1) & 3))) << 4));
    // ldmatrix V lane mapping
    int vkey = (lane & 7) + 8 * ((lane >> 3) & 1);
    int vch  = (lane >> 4);

    // ones-column B fragment for l = P·1 (n==0 column all ones)
    u32 bl = (g == 0) ? 0x3C003C00u : 0u;

    // ---- Q fragments ----
    u32 qa[2][4];
    {
        const __half* qA = g_q + ((size_t)b * TSEQ + rA) * 32;
        const __half* qB = qA + 8 * 32;
#pragma unroll
        for (int ks = 0; ks < 2; ks++) {
            qa[ks][0] = *(const u32*)(qA + 16 * ks + 2 * t4);
            qa[ks][1] = *(const u32*)(qB + 16 * ks + 2 * t4);
            qa[ks][2] = *(const u32*)(qA + 16 * ks + 2 * t4 + 8);
            qa[ks][3] = *(const u32*)(qB + 16 * ks + 2 * t4 + 8);
        }
    }

    float oc[4][4];
#pragma unroll
    for (int jd = 0; jd < 4; jd++)
#pragma unroll
        for (int q = 0; q < 4; q++) oc[jd][q] = 0.f;
    float lc[4] = {0.f, 0.f, 0.f, 0.f};   // l accumulator (col 0 meaningful)

    // ---- stage tile tb into buffer 0 ----
    {
        const char* kg = (const char*)(g_k + ((size_t)b * TSEQ + tb * 64) * 32);
        const char* vg = (const char*)(g_v + ((size_t)b * TSEQ + tb * 64) * 32);
        u32 goff = (u32)((tid >> 2) * 64 + (tid & 3) * 16);
        cpasync16(sKb[0] + stoff, kg + goff);
        cpasync16(sVb[0] + stoff, vg + goff);
        CP_COMMIT();
    }

    int cur = 0;

    for (int t = tb; t < te; t++) {
        bool havenext = (t + 1 < te);
        if (havenext) {
            const char* kg = (const char*)(g_k + ((size_t)b * TSEQ + (t + 1) * 64) * 32);
            const char* vg = (const char*)(g_v + ((size_t)b * TSEQ + (t + 1) * 64) * 32);
            u32 goff = (u32)((tid >> 2) * 64 + (tid & 3) * 16);
            cpasync16(sKb[cur ^ 1] + stoff, kg + goff);
            cpasync16(sVb[cur ^ 1] + stoff, vg + goff);
            CP_COMMIT();
            CP_WAIT(1);
        } else {
            CP_WAIT(0);
        }
        __syncthreads();

        u32 cK = sKb[cur];
        u32 cV = sVb[cur];
        bool domask = (t >= 2 * qi);

        u32 pp01 = 0, pp23 = 0;   // packed scores of even chunk, pending PV

#pragma unroll
        for (int j = 0; j < 8; j++) {
            // ---- K frags: one ldmatrix.x4 per 8-key chunk ----
            u32 kb0, kb1, kb2, kb3;
            ldsm4(kb0, kb1, kb2, kb3, cK + (u32)(j * 512) + klm);

            float sa[4] = {0.f, 0.f, 0.f, 0.f};
            mma16(sa, qa[0], kb0, kb1);
            mma16(sa, qa[1], kb2, kb3);

            // ---- mask (pre-exp) + pack to fp16 pairs ----
            int ct = t * 64 + 8 * j + 2 * t4;
            if (domask) {
                if (ct     > rA)     sa[0] = -1e30f;   // -> fp16 -inf -> exp 0
                if (ct + 1 > rA)     sa[1] = -1e30f;
                if (ct     > rA + 8) sa[2] = -1e30f;
                if (ct + 1 > rA + 8) sa[3] = -1e30f;
            }
            u32 p01 = h2pack(sa[1], sa[0]);
            u32 p23 = h2pack(sa[3], sa[2]);

            if ((j & 1) == 0) {
                pp01 = p01; pp23 = p23;
            } else {
                // ---- packed exp: P frags for the 16-key group c = j>>1 ----
                u32 pa[4];
                pa[0] = h2exp(pp01);
                pa[1] = h2exp(pp23);
                pa[2] = h2exp(p01);
                pa[3] = h2exp(p23);
                int c = j >> 1;
#pragma unroll
                for (int pr = 0; pr < 2; pr++) {
                    u32 vb0, vb1, vb2, vb3;
                    int key = c * 16 + vkey;
                    int ch  = 2 * pr + vch;
                    u32 va = cV + (u32)(key * 64 + ((ch ^ ((key >> 1) & 3)) << 4));
                    ldsm4t(vb0, vb1, vb2, vb3, va);
                    mma16(oc[2 * pr],     pa, vb0, vb1);
                    mma16(oc[2 * pr + 1], pa, vb2, vb3);
                }
                mma16(lc, pa, bl, bl);       // l += P · ones-column
            }
        }

        __syncthreads();
        cur ^= 1;
    }

    // ---- extract row sums: l lives in col 0 (t4==0 lanes), c0/c2 ----
    float ls0 = __shfl_sync(0xffffffffu, lc[0], lane & ~3);
    float ls1 = __shfl_sync(0xffffffffu, lc[2], lane & ~3);

    // ---- epilogue ----
    if (s == 1) {
        float i0 = 1.0f / ls0;
        float i1 = 1.0f / ls1;
        float* oA = out + ((size_t)b * TSEQ + rA) * 32;
        float* oB = oA + 8 * 32;
#pragma unroll
        for (int jd = 0; jd < 4; jd++) {
            *(float2*)&oA[8 * jd + 2 * t4] = make_float2(oc[jd][0] * i0, oc[jd][1] * i0);
            *(float2*)&oB[8 * jd + 2 * t4] = make_float2(oc[jd][2] * i1, oc[jd][3] * i1);
        }
    } else {
        size_t base = ((size_t)(b * 32 + qi) * 16 + p) * 128;
        int lr = 16 * w + g;
        float* pA = g_po + (base + lr) * 32;
        float* pB = pA + 8 * 32;
#pragma unroll
        for (int jd = 0; jd < 4; jd++) {
            *(float2*)&pA[8 * jd + 2 * t4] = make_float2(oc[jd][0], oc[jd][1]);
            *(float2*)&pB[8 * jd + 2 * t4] = make_float2(oc[jd][2], oc[jd][3]);
        }
        if (t4 == 0) {
            g_pl[base + lr]     = ls0;
            g_pl[base + lr + 8] = ls1;
        }
    }
}

// ---------------------------------------------------------------------------
// Kernel 3: combine split partials: out = sum_p O_p / sum_p l_p
// ---------------------------------------------------------------------------
__global__ __launch_bounds__(128) void combine_kernel(float* __restrict__ out)
{
    int qi = blockIdx.x, b = blockIdx.y, r = threadIdx.x;
    int s = nsplits(qi);
    if (s < 2) return;

    float l = 0.f;
    for (int p = 0; p < s; p++)
        l += g_pl[((size_t)(b * 32 + qi) * 16 + p) * 128 + r];
    float inv = 1.0f / l;

    float4 o[8];
#pragma unroll
    for (int j = 0; j < 8; j++) o[j] = make_float4(0.f, 0.f, 0.f, 0.f);
    for (int p = 0; p < s; p++) {
        const float4* pp = (const float4*)(g_po +
            (((size_t)(b * 32 + qi) * 16 + p) * 128 + r) * 32);
#pragma unroll
        for (int j = 0; j < 8; j++) {
            float4 a = pp[j];
            o[j].x += a.x; o[j].y += a.y; o[j].z += a.z; o[j].w += a.w;
        }
    }
    float4* op = (float4*)(out + ((size_t)b * TSEQ + qi * 128 + r) * 32);
#pragma unroll
    for (int j = 0; j < 8; j++) {
        o[j].x *= inv; o[j].y *= inv; o[j].z *= inv; o[j].w *= inv;
        op[j] = o[j];
    }
}

// ---------------------------------------------------------------------------
extern "C" void kernel_launch(void* const* d_in, const int* in_sizes, int n_in,
                              void* d_out, int out_size)
{
    const float* x  = (const float*)d_in[0];
    const float* Wq = (const float*)d_in[1];
    const float* Wk = (const float*)d_in[2];
    const float* Wv = (const float*)d_in[3];
    float* out = (float*)d_out;

    qkv_kernel<<<(BATCH * TSEQ) / 64, 128>>>(x, Wq, Wk, Wv);

    dim3 grid(272, BATCH);              // sum_i ceil((i+1)/2) = 272 per batch
    attn_kernel<<<grid, 256>>>(out);

    combine_kernel<<<dim3(32, BATCH), 128>>>(out);
}